// round 1
// baseline (speedup 1.0000x reference)
#include <cuda_runtime.h>
#include <cuda_bf16.h>
#include <cub/cub.cuh>

#define BB  90
#define LOGN 18
#define NN  (1 << LOGN)          // 262144
#define TOT (BB * NN)            // 23,592,960

// -------- static device scratch (no allocation allowed) --------
static __device__ __align__(256) unsigned long long g_ka[TOT];
static __device__ __align__(256) unsigned long long g_kb[TOT];
static __device__ __align__(256) unsigned char      g_temp[64u << 20]; // 64 MB cub temp
static __device__ __align__(256) float              g_rp[TOT];
static __device__ __align__(256) float              g_rt[TOT];
static __device__ double g_c[BB];

// -------- pack: float -> order-preserving u32, key = row|fkey|idx --------
__global__ void pack_kernel(const float* __restrict__ src) {
    int g = blockIdx.x * 256 + threadIdx.x;
    if (g >= TOT) return;
    unsigned int u = __float_as_uint(src[g]);
    u = (u & 0x80000000u) ? ~u : (u | 0x80000000u);
    unsigned int row = (unsigned int)g >> LOGN;
    unsigned int pos = (unsigned int)g & (NN - 1);
    g_ka[g] = ((unsigned long long)row << 50)
            | ((unsigned long long)u   << 18)
            | (unsigned long long)pos;
}

// -------- ranks from sorted keys; tie runs share avg rank; scatter --------
__global__ void rank_kernel(const unsigned long long* __restrict__ keys,
                            float* __restrict__ dst) {
    int g = blockIdx.x * 256 + threadIdx.x;
    if (g >= TOT) return;
    unsigned long long k  = keys[g];
    unsigned long long hi = k >> 18;   // row + float bits: defines tie groups
    int s = g, e = g;
    bool tp = (g > 0)       && ((keys[g - 1] >> 18) == hi);
    bool tn = (g < TOT - 1) && ((keys[g + 1] >> 18) == hi);
    if (tp | tn) {   // rare path: walk the run (random data => short runs)
        while (s > 0       && (keys[s - 1] >> 18) == hi) --s;
        while (e < TOT - 1 && (keys[e + 1] >> 18) == hi) ++e;
    }
    float rank = (float)((s & (NN - 1)) + (e & (NN - 1))) * 0.5f + 1.0f;
    int dstIdx = (g & ~(NN - 1)) | (int)(k & 0x3FFFFu);   // row*N + original idx
    dst[dstIdx] = rank;
}

// -------- per-row Pearson of ranks (double accumulation) --------
__global__ void corr_kernel() {
    const int row = blockIdx.x;
    const float* __restrict__ rp = g_rp + (size_t)row * NN;
    const float* __restrict__ rt = g_rt + (size_t)row * NN;
    const double m = 131072.5;   // exact rank mean (N+1)/2; invariant under ties

    double sxy = 0.0, sxx = 0.0, syy = 0.0;
    for (int i = threadIdx.x; i < NN; i += blockDim.x) {
        double x = (double)rp[i] - m;
        double y = (double)rt[i] - m;
        sxy += x * y; sxx += x * x; syy += y * y;
    }
    // warp reduce
    for (int o = 16; o; o >>= 1) {
        sxy += __shfl_down_sync(0xFFFFFFFFu, sxy, o);
        sxx += __shfl_down_sync(0xFFFFFFFFu, sxx, o);
        syy += __shfl_down_sync(0xFFFFFFFFu, syy, o);
    }
    __shared__ double sa[32], sb[32], sc[32];
    int w = threadIdx.x >> 5, lane = threadIdx.x & 31;
    if (lane == 0) { sa[w] = sxy; sb[w] = sxx; sc[w] = syy; }
    __syncthreads();
    if (w == 0) {
        int nw = blockDim.x >> 5;
        double a = (lane < nw) ? sa[lane] : 0.0;
        double b = (lane < nw) ? sb[lane] : 0.0;
        double c = (lane < nw) ? sc[lane] : 0.0;
        for (int o = 16; o; o >>= 1) {
            a += __shfl_down_sync(0xFFFFFFFFu, a, o);
            b += __shfl_down_sync(0xFFFFFFFFu, b, o);
            c += __shfl_down_sync(0xFFFFFFFFu, c, o);
        }
        if (lane == 0) g_c[row] = a / sqrt(b * c + 1e-8);
    }
}

// -------- ICIR loss from 90 correlations --------
__global__ void final_kernel(float* __restrict__ out) {
    __shared__ double sh[128];
    int t = threadIdx.x;
    double v = (t < BB) ? g_c[t] : 0.0;
    sh[t] = v;
    __syncthreads();
    for (int s = 64; s; s >>= 1) { if (t < s) sh[t] += sh[t + s]; __syncthreads(); }
    double mean = sh[0] / (double)BB;
    __syncthreads();
    double d = 0.0;
    if (t < BB) { double e = g_c[t] - mean; d = e * e; }
    sh[t] = d;
    __syncthreads();
    for (int s = 64; s; s >>= 1) { if (t < s) sh[t] += sh[t + s]; __syncthreads(); }
    if (t == 0) {
        double sd = sqrt(sh[0] / (double)BB) + 1e-8;
        double loss = -(mean / sd) + 0.1 * sd;
        out[0] = (float)loss;
    }
}

extern "C" void kernel_launch(void* const* d_in, const int* in_sizes, int n_in,
                              void* d_out, int out_size) {
    const float* pred = (const float*)d_in[0];
    const float* trueY = (const float*)d_in[1];

    unsigned long long *ka, *kb;
    unsigned char* tmp;
    float *rp, *rt;
    cudaGetSymbolAddress((void**)&ka,  g_ka);
    cudaGetSymbolAddress((void**)&kb,  g_kb);
    cudaGetSymbolAddress((void**)&tmp, g_temp);
    cudaGetSymbolAddress((void**)&rp,  g_rp);
    cudaGetSymbolAddress((void**)&rt,  g_rt);

    const int TPB = 256;
    const int NBL = (TOT + TPB - 1) / TPB;

    // ---- pred: pack -> sort (39 bits: [18,57)) -> ranks ----
    pack_kernel<<<NBL, TPB>>>(pred);
    {
        cub::DoubleBuffer<unsigned long long> db(ka, kb);
        size_t tb = 0;
        cub::DeviceRadixSort::SortKeys(nullptr, tb, db, TOT, 18, 57, (cudaStream_t)0);
        if (tb > (size_t)(64u << 20)) return;  // would corrupt; bail (never expected)
        cub::DeviceRadixSort::SortKeys(tmp, tb, db, TOT, 18, 57, (cudaStream_t)0);
        rank_kernel<<<NBL, TPB>>>(db.Current(), rp);
    }

    // ---- true: pack -> sort -> ranks ----
    pack_kernel<<<NBL, TPB>>>(trueY);
    {
        cub::DoubleBuffer<unsigned long long> db(ka, kb);
        size_t tb = 0;
        cub::DeviceRadixSort::SortKeys(nullptr, tb, db, TOT, 18, 57, (cudaStream_t)0);
        if (tb > (size_t)(64u << 20)) return;
        cub::DeviceRadixSort::SortKeys(tmp, tb, db, TOT, 18, 57, (cudaStream_t)0);
        rank_kernel<<<NBL, TPB>>>(db.Current(), rt);
    }

    // ---- correlations + loss ----
    corr_kernel<<<BB, 1024>>>();
    final_kernel<<<1, 128>>>((float*)d_out);
}

// round 2
// speedup vs baseline: 1.3606x; 1.3606x over previous
#include <cuda_runtime.h>
#include <cuda_bf16.h>
#include <cub/cub.cuh>

#define BB   90
#define LOGN 18
#define NN   (1 << LOGN)          // 262144
#define TOT  (BB * NN)            // 23,592,960

// -------- static device scratch (no allocation allowed) --------
static __device__ __align__(256) unsigned long long g_ka[TOT];
static __device__ __align__(256) unsigned long long g_kb[TOT];
static __device__ __align__(256) unsigned char      g_temp[64u << 20];
static __device__ __align__(256) unsigned int       g_rp2[TOT];       // 2*rank of pred
static __device__ unsigned long long g_sxx[BB];
static __device__ unsigned long long g_syy[BB];
static __device__ unsigned long long g_sxy[BB];

// key layout: [row:7 @50] [ordered_float:32 @18] [idx:18 @0]
// sorted bits: [25,57) = row + top 25 float bits (4 radix passes)

__device__ __forceinline__ unsigned int fkey(float f) {
    unsigned int u = __float_as_uint(f);
    return (u & 0x80000000u) ? ~u : (u | 0x80000000u);
}

__global__ void zero_sums_kernel() {
    int t = threadIdx.x;
    if (t < BB) { g_sxx[t] = 0ull; g_syy[t] = 0ull; g_sxy[t] = 0ull; }
}

// -------- pack: 4 elements / thread --------
__global__ void pack_kernel(const float4* __restrict__ src) {
    int q = blockIdx.x * 256 + threadIdx.x;           // quad index
    if (q >= TOT / 4) return;
    float4 v = src[q];
    int g0 = q * 4;
    unsigned long long rowbits = (unsigned long long)((unsigned)g0 >> LOGN) << 50;
    unsigned int pos0 = (unsigned)g0 & (NN - 1);      // quads never straddle rows
    g_ka[g0 + 0] = rowbits | ((unsigned long long)fkey(v.x) << 18) | (pos0 + 0);
    g_ka[g0 + 1] = rowbits | ((unsigned long long)fkey(v.y) << 18) | (pos0 + 1);
    g_ka[g0 + 2] = rowbits | ((unsigned long long)fkey(v.z) << 18) | (pos0 + 2);
    g_ka[g0 + 3] = rowbits | ((unsigned long long)fkey(v.w) << 18) | (pos0 + 3);
}

// -------- block i64 reduce helper --------
__device__ __forceinline__ long long block_reduce_ll(long long v, long long* sh) {
    for (int o = 16; o; o >>= 1) v += __shfl_down_sync(0xFFFFFFFFu, v, o);
    int w = threadIdx.x >> 5, lane = threadIdx.x & 31;
    if (lane == 0) sh[w] = v;
    __syncthreads();
    if (w == 0) {
        v = (lane < (int)(blockDim.x >> 5)) ? sh[lane] : 0ll;
        for (int o = 16; o; o >>= 1) v += __shfl_down_sync(0xFFFFFFFFu, v, o);
    }
    return v;   // valid in thread 0
}

// -------- compute 2*rank for element at sorted position g --------
__device__ __forceinline__ int rank2_of(const unsigned long long* __restrict__ keys,
                                        int g, unsigned long long k) {
    unsigned long long hi = k >> 25;
    int pos = g & (NN - 1);
    bool tp = (g > 0)       && ((keys[g - 1] >> 25) == hi);
    bool tn = (g < TOT - 1) && ((keys[g + 1] >> 25) == hi);
    int c_less = 0, c_eq = 1, s = g;
    if (tp | tn) {
        int e = g;
        while (s > 0       && (keys[s - 1] >> 25) == hi) --s;
        while (e < TOT - 1 && (keys[e + 1] >> 25) == hi) ++e;
        unsigned int fk = (unsigned int)(k >> 18);
        c_less = 0; c_eq = 0;
        for (int j = s; j <= e; ++j) {
            unsigned int fj = (unsigned int)(keys[j] >> 18);
            c_less += (fj < fk);
            c_eq   += (fj == fk);
        }
    }
    // 2*rank = 2*run_start_pos + 2*c_less + (c_eq-1) + 2
    return 2 * (s & (NN - 1)) + 2 * c_less + (c_eq - 1) + 2;
}

// -------- rank A: write 2*rank(pred), accumulate sum of squares --------
__global__ void rankA_kernel(const unsigned long long* __restrict__ keys) {
    __shared__ long long sh[32];
    int g = blockIdx.x * 1024 + threadIdx.x;           // blocks never straddle rows
    unsigned long long k = keys[g];
    int r2 = rank2_of(keys, g, k);
    int row = blockIdx.x >> 8;                          // 1024*256 = NN
    int idx = (int)(k & 0x3FFFFu);
    g_rp2[row * NN + idx] = (unsigned int)r2;
    long long sq = (long long)r2 * (long long)r2;
    sq = block_reduce_ll(sq, sh);
    if (threadIdx.x == 0) atomicAdd(&g_sxx[row], (unsigned long long)sq);
}

// -------- rank B: 2*rank(true), gather pred rank, accumulate syy/sxy --------
__global__ void rankB_kernel(const unsigned long long* __restrict__ keys) {
    __shared__ long long sh[32];
    int g = blockIdx.x * 1024 + threadIdx.x;
    unsigned long long k = keys[g];
    int r2 = rank2_of(keys, g, k);
    int row = blockIdx.x >> 8;
    int idx = (int)(k & 0x3FFFFu);
    long long u = (long long)g_rp2[row * NN + idx];
    long long v = (long long)r2;
    long long syy = v * v;
    long long sxy = u * v;
    syy = block_reduce_ll(syy, sh);
    __syncthreads();
    sxy = block_reduce_ll(sxy, sh);
    if (threadIdx.x == 0) {
        atomicAdd(&g_syy[row], (unsigned long long)syy);
        atomicAdd(&g_sxy[row], (unsigned long long)sxy);
    }
}

// -------- final: per-row corr -> ICIR loss --------
__global__ void final_kernel(float* __restrict__ out) {
    __shared__ double sh[128];
    int t = threadIdx.x;
    double c = 0.0;
    if (t < BB) {
        const long long C = (long long)NN * (long long)(NN + 1) * (long long)(NN + 1);
        double sxx = (double)((long long)g_sxx[t] - C) * 0.25;   // rank-scale centered
        double syy = (double)((long long)g_syy[t] - C) * 0.25;
        double sxy = (double)((long long)g_sxy[t] - C) * 0.25;
        c = sxy / sqrt(sxx * syy + 1e-8);
    }
    sh[t] = c;
    __syncthreads();
    for (int s = 64; s; s >>= 1) { if (t < s) sh[t] += sh[t + s]; __syncthreads(); }
    double mean = sh[0] / (double)BB;
    __syncthreads();
    double d = 0.0;
    if (t < BB) { double e = c - mean; d = e * e; }
    sh[t] = d;
    __syncthreads();
    for (int s = 64; s; s >>= 1) { if (t < s) sh[t] += sh[t + s]; __syncthreads(); }
    if (t == 0) {
        double sd = sqrt(sh[0] / (double)BB) + 1e-8;
        out[0] = (float)(-(mean / sd) + 0.1 * sd);
    }
}

extern "C" void kernel_launch(void* const* d_in, const int* in_sizes, int n_in,
                              void* d_out, int out_size) {
    const float* pred  = (const float*)d_in[0];
    const float* trueY = (const float*)d_in[1];

    unsigned long long *ka, *kb;
    unsigned char* tmp;
    cudaGetSymbolAddress((void**)&ka,  g_ka);
    cudaGetSymbolAddress((void**)&kb,  g_kb);
    cudaGetSymbolAddress((void**)&tmp, g_temp);

    const int PACK_BLKS = (TOT / 4 + 255) / 256;
    const int RANK_BLKS = TOT / 1024;

    zero_sums_kernel<<<1, 128>>>();

    // ---- pred: pack -> 4-pass sort (bits [25,57)) -> ranks+sums ----
    pack_kernel<<<PACK_BLKS, 256>>>((const float4*)pred);
    {
        cub::DoubleBuffer<unsigned long long> db(ka, kb);
        size_t tb = 0;
        cub::DeviceRadixSort::SortKeys(nullptr, tb, db, TOT, 25, 57, (cudaStream_t)0);
        if (tb > (size_t)(64u << 20)) return;
        cub::DeviceRadixSort::SortKeys(tmp, tb, db, TOT, 25, 57, (cudaStream_t)0);
        rankA_kernel<<<RANK_BLKS, 1024>>>(db.Current());
    }

    // ---- true: pack -> sort -> ranks+sums ----
    pack_kernel<<<PACK_BLKS, 256>>>((const float4*)trueY);
    {
        cub::DoubleBuffer<unsigned long long> db(ka, kb);
        size_t tb = 0;
        cub::DeviceRadixSort::SortKeys(nullptr, tb, db, TOT, 25, 57, (cudaStream_t)0);
        if (tb > (size_t)(64u << 20)) return;
        cub::DeviceRadixSort::SortKeys(tmp, tb, db, TOT, 25, 57, (cudaStream_t)0);
        rankB_kernel<<<RANK_BLKS, 1024>>>(db.Current());
    }

    final_kernel<<<1, 128>>>((float*)d_out);
}

// round 3
// speedup vs baseline: 2.4231x; 1.7809x over previous
#include <cuda_runtime.h>
#include <cuda_bf16.h>
#include <cub/cub.cuh>

#define BB   90
#define LOGN 18
#define NN   (1 << LOGN)           // 262144
#define TOT  (BB * NN)             // 23,592,960
#define DIGB 18
#define NB   (1 << DIGB)           // buckets per row per array
#define NHIST (2 * BB * NB)        // 47,185,920 (= 2*TOT)

// -------- static device scratch --------
static __device__ __align__(256) unsigned int       g_hist[NHIST];     // 189 MB
static __device__ __align__(256) unsigned long long g_keys[2 * TOT];   // 378 MB
static __device__ __align__(256) unsigned int       g_rp2[TOT];        // 94 MB
static __device__ __align__(256) unsigned char      g_temp[32u << 20];
static __device__ unsigned long long g_sxx[BB], g_syy[BB], g_sxy[BB];

// -------- monotone helpers --------
__device__ __forceinline__ unsigned int fkey(float f) {
    unsigned int u = __float_as_uint(f);
    return (u & 0x80000000u) ? ~u : (u | 0x80000000u);
}
__device__ __forceinline__ float inv_fkey(unsigned int fk) {
    unsigned int u = (fk & 0x80000000u) ? (fk & 0x7FFFFFFFu) : ~fk;
    return __uint_as_float(u);
}
// exactly weakly-monotone bucketization: x1<x2 => d1<=d2, equal x => equal d
__device__ __forceinline__ unsigned int digit_of(float x) {
    float t = fmaf(x, 32768.0f, 131072.0f);     // covers [-4,4) at 2^-15 step
    t = fminf(fmaxf(t, 0.0f), 262143.0f);       // tails & non-finites -> edge buckets
    return (unsigned int)t;
}

__global__ void zero_sums_kernel() {
    int t = threadIdx.x;
    if (t < BB) { g_sxx[t] = 0ull; g_syy[t] = 0ull; g_sxy[t] = 0ull; }
}

// -------- pass 1: histogram both arrays (RED.ADD, no return) --------
__global__ void hist_kernel(const float4* __restrict__ p, const float4* __restrict__ t) {
    int q = blockIdx.x * 256 + threadIdx.x;          // quad index, exact grid
    float4 a = p[q], b = t[q];
    unsigned int row = (unsigned int)q >> (LOGN - 2);
    unsigned int ba = row << DIGB;
    unsigned int bb = (unsigned int)TOT + (row << DIGB);
    atomicAdd(&g_hist[ba + digit_of(a.x)], 1u);
    atomicAdd(&g_hist[ba + digit_of(a.y)], 1u);
    atomicAdd(&g_hist[ba + digit_of(a.z)], 1u);
    atomicAdd(&g_hist[ba + digit_of(a.w)], 1u);
    atomicAdd(&g_hist[bb + digit_of(b.x)], 1u);
    atomicAdd(&g_hist[bb + digit_of(b.y)], 1u);
    atomicAdd(&g_hist[bb + digit_of(b.z)], 1u);
    atomicAdd(&g_hist[bb + digit_of(b.w)], 1u);
}

// -------- pass 2: scatter keys to bucket slots --------
__global__ void scatter_kernel(const float4* __restrict__ p, const float4* __restrict__ t) {
    int q = blockIdx.x * 256 + threadIdx.x;
    float4 a = p[q], b = t[q];
    unsigned int row  = (unsigned int)q >> (LOGN - 2);
    unsigned int idx0 = ((unsigned int)q << 2) & (NN - 1);
    unsigned int ba = row << DIGB;
    unsigned int bb = (unsigned int)TOT + (row << DIGB);
    float av[4] = {a.x, a.y, a.z, a.w};
    float bv[4] = {b.x, b.y, b.z, b.w};
#pragma unroll
    for (int j = 0; j < 4; ++j) {
        unsigned int pos = atomicAdd(&g_hist[ba + digit_of(av[j])], 1u);
        g_keys[pos] = ((unsigned long long)fkey(av[j]) << 18) | (idx0 + j);
    }
#pragma unroll
    for (int j = 0; j < 4; ++j) {
        unsigned int pos = atomicAdd(&g_hist[bb + digit_of(bv[j])], 1u);
        g_keys[pos] = ((unsigned long long)fkey(bv[j]) << 18) | (idx0 + j);
    }
}

// -------- block i64 reduce --------
__device__ __forceinline__ long long block_reduce_ll(long long v, long long* sh) {
    for (int o = 16; o; o >>= 1) v += __shfl_down_sync(0xFFFFFFFFu, v, o);
    int w = threadIdx.x >> 5, lane = threadIdx.x & 31;
    if (lane == 0) sh[w] = v;
    __syncthreads();
    if (w == 0) {
        v = (lane < (int)(blockDim.x >> 5)) ? sh[lane] : 0ll;
        for (int o = 16; o; o >>= 1) v += __shfl_down_sync(0xFFFFFFFFu, v, o);
    }
    return v;   // valid in thread 0
}

// 2*rank of bucketed element: bucket [s,e) from (post-scatter) hist ends
__device__ __forceinline__ int rank2_of(unsigned int s, unsigned int e,
                                        unsigned int fk, unsigned int row) {
    int c_less = 0, c_eq = 1;
    if (e - s > 1u) {
        c_eq = 0;
        for (unsigned int j = s; j < e; ++j) {
            unsigned int fj = (unsigned int)(__ldg(&g_keys[j]) >> 18);
            c_less += (fj < fk);
            c_eq   += (fj == fk);
        }
    }
    unsigned int locals = s - (row << LOGN);
    return 2 * (int)locals + 2 * c_less + c_eq + 1;   // = 2*tie-avg-rank
}

// -------- pass 3a: pred ranks --------
__global__ void rankA_kernel() {
    __shared__ long long sh[16];
    int g = blockIdx.x * 512 + threadIdx.x;            // blocks never straddle rows
    unsigned long long k = g_keys[g];
    unsigned int fk = (unsigned int)(k >> 18);
    unsigned int row = (unsigned int)g >> LOGN;
    unsigned int b = (row << DIGB) + digit_of(inv_fkey(fk));
    unsigned int s = b ? g_hist[b - 1] : 0u;
    unsigned int e = g_hist[b];
    int r2 = rank2_of(s, e, fk, row);
    g_rp2[(row << LOGN) + (unsigned int)(k & 0x3FFFFu)] = (unsigned int)r2;
    long long sq = (long long)r2 * (long long)r2;
    sq = block_reduce_ll(sq, sh);
    if (threadIdx.x == 0) atomicAdd(&g_sxx[row], (unsigned long long)sq);
}

// -------- pass 3b: true ranks + gather pred + sums --------
__global__ void rankB_kernel() {
    __shared__ long long sh[16];
    int g = blockIdx.x * 512 + threadIdx.x;            // local index in B half
    unsigned long long k = g_keys[TOT + g];
    unsigned int fk = (unsigned int)(k >> 18);
    unsigned int row = (unsigned int)g >> LOGN;
    unsigned int b = (unsigned int)TOT + (row << DIGB) + digit_of(inv_fkey(fk));
    unsigned int s = g_hist[b - 1];                    // b >= TOT > 0 always
    unsigned int e = g_hist[b];
    // positions in B half are global (offset TOT); localize to row:
    int c_less = 0, c_eq = 1;
    if (e - s > 1u) {
        c_eq = 0;
        for (unsigned int j = s; j < e; ++j) {
            unsigned int fj = (unsigned int)(__ldg(&g_keys[j]) >> 18);
            c_less += (fj < fk);
            c_eq   += (fj == fk);
        }
    }
    unsigned int locals = s - (unsigned int)TOT - (row << LOGN);
    int r2 = 2 * (int)locals + 2 * c_less + c_eq + 1;
    long long v = (long long)r2;
    long long u = (long long)g_rp2[(row << LOGN) + (unsigned int)(k & 0x3FFFFu)];
    long long syy = v * v;
    long long sxy = u * v;
    syy = block_reduce_ll(syy, sh);
    __syncthreads();
    sxy = block_reduce_ll(sxy, sh);
    if (threadIdx.x == 0) {
        atomicAdd(&g_syy[row], (unsigned long long)syy);
        atomicAdd(&g_sxy[row], (unsigned long long)sxy);
    }
}

// -------- final: per-row corr -> ICIR loss --------
__global__ void final_kernel(float* __restrict__ out) {
    __shared__ double sh[128];
    int t = threadIdx.x;
    double c = 0.0;
    if (t < BB) {
        const long long C = (long long)NN * (long long)(NN + 1) * (long long)(NN + 1);
        double sxx = (double)((long long)g_sxx[t] - C) * 0.25;
        double syy = (double)((long long)g_syy[t] - C) * 0.25;
        double sxy = (double)((long long)g_sxy[t] - C) * 0.25;
        c = sxy / sqrt(sxx * syy + 1e-8);
    }
    sh[t] = c;
    __syncthreads();
    for (int s = 64; s; s >>= 1) { if (t < s) sh[t] += sh[t + s]; __syncthreads(); }
    double mean = sh[0] / (double)BB;
    __syncthreads();
    double d = 0.0;
    if (t < BB) { double e = c - mean; d = e * e; }
    sh[t] = d;
    __syncthreads();
    for (int s = 64; s; s >>= 1) { if (t < s) sh[t] += sh[t + s]; __syncthreads(); }
    if (t == 0) {
        double sd = sqrt(sh[0] / (double)BB) + 1e-8;
        out[0] = (float)(-(mean / sd) + 0.1 * sd);
    }
}

extern "C" void kernel_launch(void* const* d_in, const int* in_sizes, int n_in,
                              void* d_out, int out_size) {
    const float* pred  = (const float*)d_in[0];
    const float* trueY = (const float*)d_in[1];

    unsigned int*  hist;
    unsigned char* tmp;
    cudaGetSymbolAddress((void**)&hist, g_hist);
    cudaGetSymbolAddress((void**)&tmp,  g_temp);

    cudaStream_t s0 = (cudaStream_t)0;
    const int QBLKS = (TOT / 4) / 256;    // 23040, exact
    const int RBLKS = TOT / 512;          // 46080, exact

    cudaMemsetAsync(hist, 0, (size_t)NHIST * sizeof(unsigned int), s0);
    zero_sums_kernel<<<1, 128, 0, s0>>>();

    hist_kernel<<<QBLKS, 256, 0, s0>>>((const float4*)pred, (const float4*)trueY);

    {   // global exclusive scan -> bucket start offsets (in-place)
        size_t tb = 0;
        cub::DeviceScan::ExclusiveSum(nullptr, tb, hist, hist, NHIST, s0);
        if (tb > (size_t)(32u << 20)) return;
        cub::DeviceScan::ExclusiveSum(tmp, tb, hist, hist, NHIST, s0);
    }

    scatter_kernel<<<QBLKS, 256, 0, s0>>>((const float4*)pred, (const float4*)trueY);

    rankA_kernel<<<RBLKS, 512, 0, s0>>>();
    rankB_kernel<<<RBLKS, 512, 0, s0>>>();
    final_kernel<<<1, 128, 0, s0>>>((float*)d_out);
}

// round 4
// speedup vs baseline: 2.4601x; 1.0153x over previous
#include <cuda_runtime.h>
#include <cuda_bf16.h>
#include <cub/cub.cuh>

#define BB   90
#define LOGN 18
#define NN   (1 << LOGN)           // 262144
#define TOT  (BB * NN)             // 23,592,960
#define DIGB 18
#define NB   (1 << DIGB)
#define NHIST (2 * BB * NB)        // 47,185,920

// -------- static device scratch --------
static __device__ __align__(256) unsigned int  g_hist[NHIST];   // 189 MB
static __device__ __align__(256) unsigned int  g_fk[2 * TOT];   // 189 MB (bucketed fkeys)
static __device__ __align__(256) unsigned char g_temp[32u << 20];
static __device__ unsigned long long g_sxx[BB], g_syy[BB], g_sxy[BB];

__device__ __forceinline__ unsigned int fkey(float f) {
    f = f + 0.0f;                               // canonicalize -0 -> +0
    unsigned int u = __float_as_uint(f);
    return (u & 0x80000000u) ? ~u : (u | 0x80000000u);
}
// exactly weakly-monotone bucketization (ties never split across buckets)
__device__ __forceinline__ unsigned int digit_of(float x) {
    float t = fmaf(x, 32768.0f, 131072.0f);
    t = fminf(fmaxf(t, 0.0f), 262143.0f);
    return (unsigned int)t;
}

__global__ void zero_sums_kernel() {
    int t = threadIdx.x;
    if (t < BB) { g_sxx[t] = 0ull; g_syy[t] = 0ull; g_sxy[t] = 0ull; }
}

// -------- pass 1: histogram both arrays --------
__global__ void hist_kernel(const float4* __restrict__ p, const float4* __restrict__ t) {
    int q = blockIdx.x * 256 + threadIdx.x;
    float4 a = p[q], b = t[q];
    unsigned int row = (unsigned int)q >> (LOGN - 2);
    unsigned int ba = row << DIGB;
    unsigned int bb = (unsigned int)(BB << DIGB) + (row << DIGB);
    atomicAdd(&g_hist[ba + digit_of(a.x)], 1u);
    atomicAdd(&g_hist[ba + digit_of(a.y)], 1u);
    atomicAdd(&g_hist[ba + digit_of(a.z)], 1u);
    atomicAdd(&g_hist[ba + digit_of(a.w)], 1u);
    atomicAdd(&g_hist[bb + digit_of(b.x)], 1u);
    atomicAdd(&g_hist[bb + digit_of(b.y)], 1u);
    atomicAdd(&g_hist[bb + digit_of(b.z)], 1u);
    atomicAdd(&g_hist[bb + digit_of(b.w)], 1u);
}

// -------- pass 2: scatter 4-byte fkeys into bucket slots --------
__global__ void scatter_kernel(const float4* __restrict__ p, const float4* __restrict__ t) {
    int q = blockIdx.x * 256 + threadIdx.x;
    float4 a = p[q], b = t[q];
    unsigned int row = (unsigned int)q >> (LOGN - 2);
    unsigned int ba = row << DIGB;
    unsigned int bb = (unsigned int)(BB << DIGB) + (row << DIGB);
    float av[4] = {a.x, a.y, a.z, a.w};
    float bv[4] = {b.x, b.y, b.z, b.w};
#pragma unroll
    for (int j = 0; j < 4; ++j) {
        unsigned int pos = atomicAdd(&g_hist[ba + digit_of(av[j])], 1u);
        g_fk[pos] = fkey(av[j]);
    }
#pragma unroll
    for (int j = 0; j < 4; ++j) {
        unsigned int pos = atomicAdd(&g_hist[bb + digit_of(bv[j])], 1u);
        g_fk[pos] = fkey(bv[j]);
    }
}

__device__ __forceinline__ long long block_reduce_ll(long long v, long long* sh) {
    for (int o = 16; o; o >>= 1) v += __shfl_down_sync(0xFFFFFFFFu, v, o);
    int w = threadIdx.x >> 5, lane = threadIdx.x & 31;
    if (lane == 0) sh[w] = v;
    __syncthreads();
    if (w == 0) {
        v = (lane < (int)(blockDim.x >> 5)) ? sh[lane] : 0ll;
        for (int o = 16; o; o >>= 1) v += __shfl_down_sync(0xFFFFFFFFu, v, o);
    }
    return v;
}

// 2*rank from bucket [s,e): walk fkeys (post-scatter hist holds bucket ENDS)
__device__ __forceinline__ int rank2_walk(unsigned int s, unsigned int e,
                                          unsigned int fk, unsigned int base) {
    int c_less = 0, c_eq = 1;
    if (e - s > 1u) {
        c_eq = 0;
        for (unsigned int i = s; i < e; ++i) {
            unsigned int f = __ldg(&g_fk[i]);
            c_less += (f < fk);
            c_eq   += (f == fk);
        }
    }
    return 2 * (int)(s - base) + 2 * c_less + c_eq + 1;
}

// -------- pass 3 (fused): ranks for pred & true + all moment sums --------
__global__ void rank_kernel(const float4* __restrict__ p, const float4* __restrict__ t) {
    __shared__ long long sh[8];
    int q = blockIdx.x * 256 + threadIdx.x;
    float4 a = p[q], b = t[q];
    unsigned int row = (unsigned int)q >> (LOGN - 2);     // 256 blocks/row exactly
    unsigned int rowl = row << LOGN;
    float av[4] = {a.x, a.y, a.z, a.w};
    float bv[4] = {b.x, b.y, b.z, b.w};
    long long sxx = 0, syy = 0, sxy = 0;
#pragma unroll
    for (int j = 0; j < 4; ++j) {
        // pred
        unsigned int fk = fkey(av[j]);
        unsigned int bk = (row << DIGB) + digit_of(av[j]);
        unsigned int s  = bk ? __ldg(&g_hist[bk - 1]) : 0u;
        unsigned int e  = __ldg(&g_hist[bk]);
        int r2p = rank2_walk(s, e, fk, rowl);
        // true
        unsigned int fk2 = fkey(bv[j]);
        unsigned int bk2 = (unsigned int)(BB << DIGB) + (row << DIGB) + digit_of(bv[j]);
        unsigned int s2  = __ldg(&g_hist[bk2 - 1]);       // always valid (bk2 > 0)
        unsigned int e2  = __ldg(&g_hist[bk2]);
        int r2t = rank2_walk(s2, e2, fk2, (unsigned int)TOT + rowl);
        sxx += (long long)r2p * r2p;
        syy += (long long)r2t * r2t;
        sxy += (long long)r2p * r2t;
    }
    sxx = block_reduce_ll(sxx, sh); __syncthreads();
    syy = block_reduce_ll(syy, sh); __syncthreads();
    sxy = block_reduce_ll(sxy, sh);
    if (threadIdx.x == 0) {
        atomicAdd(&g_sxx[row], (unsigned long long)sxx);
        atomicAdd(&g_syy[row], (unsigned long long)syy);
        atomicAdd(&g_sxy[row], (unsigned long long)sxy);
    }
}

// -------- final: per-row corr -> ICIR loss --------
__global__ void final_kernel(float* __restrict__ out) {
    __shared__ double sh[128];
    int t = threadIdx.x;
    double c = 0.0;
    if (t < BB) {
        const long long C = (long long)NN * (long long)(NN + 1) * (long long)(NN + 1);
        double sxx = (double)((long long)g_sxx[t] - C) * 0.25;
        double syy = (double)((long long)g_syy[t] - C) * 0.25;
        double sxy = (double)((long long)g_sxy[t] - C) * 0.25;
        c = sxy / sqrt(sxx * syy + 1e-8);
    }
    sh[t] = c;
    __syncthreads();
    for (int s = 64; s; s >>= 1) { if (t < s) sh[t] += sh[t + s]; __syncthreads(); }
    double mean = sh[0] / (double)BB;
    __syncthreads();
    double d = 0.0;
    if (t < BB) { double e = c - mean; d = e * e; }
    sh[t] = d;
    __syncthreads();
    for (int s = 64; s; s >>= 1) { if (t < s) sh[t] += sh[t + s]; __syncthreads(); }
    if (t == 0) {
        double sd = sqrt(sh[0] / (double)BB) + 1e-8;
        out[0] = (float)(-(mean / sd) + 0.1 * sd);
    }
}

extern "C" void kernel_launch(void* const* d_in, const int* in_sizes, int n_in,
                              void* d_out, int out_size) {
    const float* pred  = (const float*)d_in[0];
    const float* trueY = (const float*)d_in[1];

    unsigned int*  hist;
    unsigned char* tmp;
    cudaGetSymbolAddress((void**)&hist, g_hist);
    cudaGetSymbolAddress((void**)&tmp,  g_temp);

    cudaStream_t s0 = (cudaStream_t)0;
    const int QBLKS = (TOT / 4) / 256;    // 23040 exact

    cudaMemsetAsync(hist, 0, (size_t)NHIST * sizeof(unsigned int), s0);
    zero_sums_kernel<<<1, 128, 0, s0>>>();

    hist_kernel<<<QBLKS, 256, 0, s0>>>((const float4*)pred, (const float4*)trueY);

    {
        size_t tb = 0;
        cub::DeviceScan::ExclusiveSum(nullptr, tb, hist, hist, NHIST, s0);
        if (tb > (size_t)(32u << 20)) return;
        cub::DeviceScan::ExclusiveSum(tmp, tb, hist, hist, NHIST, s0);
    }

    scatter_kernel<<<QBLKS, 256, 0, s0>>>((const float4*)pred, (const float4*)trueY);
    rank_kernel<<<QBLKS, 256, 0, s0>>>((const float4*)pred, (const float4*)trueY);
    final_kernel<<<1, 128, 0, s0>>>((float*)d_out);
}